// round 14
// baseline (speedup 1.0000x reference)
#include <cuda_runtime.h>
#include <cuda_bf16.h>
#include <cstdint>

// Shapes (fixed)
#define B 512
#define S 256
#define EMB 256
#define FEAT 512
#define HID 1024
#define OUT_ACT 14
#define KG 1536                    // gates GEMM K after emb fold: FEAT + HID
#define NGATES 4096

typedef __nv_bfloat16 bf16;

// ---------------------------------------------------------------------------
// Scratch (device globals; no allocation allowed)
// ---------------------------------------------------------------------------
__device__ float g_th[B * 2 * HID];      // [target | half2]  (fused GEMM output)
__device__ float g_htilde[B * HID];
__device__ float g_embW[16 * NGATES];    // emb@W_ih[:,:256]^T + biases, PERMUTED cols (4j+gate)
__device__ int   g_mask_is_u8;

// bf16 hi/lo split buffers
__device__ bf16 gAg_hi[B * KG],         gAg_lo[B * KG];           // [feature|h0]
__device__ bf16 gWg_hi[NGATES * KG],    gWg_lo[NGATES * KG];      // permuted gates W
__device__ bf16 gAh_hi[B * HID],        gAh_lo[B * HID];          // h1
__device__ bf16 gAw_hi[B * HID],        gAw_lo[B * HID];          // weighted
__device__ bf16 gWcat_hi[2 * HID * HID], gWcat_lo[2 * HID * HID]; // [W_in ; W_out[:,1024:]]
__device__ bf16 gWoa_hi[HID * HID],     gWoa_lo[HID * HID];       // W_out[:, :1024]

__device__ __forceinline__ float sigmoidf_(float x) { return 1.0f / (1.0f + expf(-x)); }

__device__ __forceinline__ void split2(float v, bf16& h, bf16& l) {
    h = __float2bfloat16(v);
    l = __float2bfloat16(v - __bfloat162float(h));
}

// ---------------------------------------------------------------------------
// PTX helpers
// ---------------------------------------------------------------------------
__device__ __forceinline__ uint32_t smem_u32(const void* p) {
    uint32_t a;
    asm("{ .reg .u64 t; cvta.to.shared.u64 t, %1; cvt.u32.u64 %0, t; }" : "=r"(a) : "l"(p));
    return a;
}
__device__ __forceinline__ void cp16(uint32_t saddr, const void* g) {
    asm volatile("cp.async.cg.shared.global [%0], [%1], 16;\n" :: "r"(saddr), "l"(g));
}
__device__ __forceinline__ void cp_commit() { asm volatile("cp.async.commit_group;\n" ::: "memory"); }
template <int N>
__device__ __forceinline__ void cp_wait() { asm volatile("cp.async.wait_group %0;\n" :: "n"(N) : "memory"); }

__device__ __forceinline__ void ldsm4(uint32_t& r0, uint32_t& r1, uint32_t& r2, uint32_t& r3,
                                      uint32_t addr) {
    asm volatile("ldmatrix.sync.aligned.m8n8.x4.shared.b16 {%0,%1,%2,%3}, [%4];"
        : "=r"(r0), "=r"(r1), "=r"(r2), "=r"(r3) : "r"(addr));
}
__device__ __forceinline__ void mma16816(float* c, const uint32_t* a, const uint32_t* b) {
    asm volatile(
        "mma.sync.aligned.m16n8k16.row.col.f32.bf16.bf16.f32 "
        "{%0,%1,%2,%3},{%4,%5,%6,%7},{%8,%9},{%0,%1,%2,%3};"
        : "+f"(c[0]), "+f"(c[1]), "+f"(c[2]), "+f"(c[3])
        : "r"(a[0]), "r"(a[1]), "r"(a[2]), "r"(a[3]), "r"(b[0]), "r"(b[1]));
}

// ---------------------------------------------------------------------------
// split-bf16 GEMM (mma.sync + ldmatrix + NS-stage cp.async)
// BIAS: 0 none, 1 action table btab[action[row]][col] (stride N),
//       2 elementwise btab[row*ldbias + col].
// ACT:  0 none, 1 tanh, 2 LSTM epilogue (permuted 4j+gate layout):
//       lane-pair shfl exchange -> c1/h1 -> writes h1_out(C), c1_out, gAh splits.
// ---------------------------------------------------------------------------
template <int BM, int BN, int WGM, int WGN, int NS, int NTHR, int BIAS, int ACT>
__global__ __launch_bounds__(NTHR)
void tc_gemm(const bf16* __restrict__ Ahi, const bf16* __restrict__ Alo,
             const bf16* __restrict__ Bhi, const bf16* __restrict__ Blo,
             const int* __restrict__ action, const float* __restrict__ btab,
             int ldbias, const float* __restrict__ c0_in, float* __restrict__ c1_out,
             float* __restrict__ C, int N, int K)
{
    constexpr int WH  = BM / WGM, WN = BN / WGN;
    constexpr int MT  = WH / 16,  NTC = WN / 8;
    constexpr int STAGE   = (2 * BM + 2 * BN) * 80;
    constexpr int OFF_ALO = BM * 80;
    constexpr int OFF_BHI = 2 * BM * 80;
    constexpr int ROWS    = 2 * BM + 2 * BN;
    constexpr int CHUNKS  = ROWS * 4;          // 16B chunks per stage

    extern __shared__ char sm[];
    const int tid  = threadIdx.x;
    const int warp = tid >> 5, lane = tid & 31;
    const int warpM = warp / WGN, warpN = warp % WGN;
    const int lr = lane >> 2, lc = lane & 3;
    const int m0 = blockIdx.y * BM;
    const int n0 = blockIdx.x * BN;
    const uint32_t sb0 = smem_u32(sm);

    float acc[MT][NTC][4] = {};

    const int nc = K >> 5;    // BK=32

    auto load_stage = [&](int buf, int kblk) {
        uint32_t sb = sb0 + buf * STAGE;
        #pragma unroll
        for (int j = 0; j < CHUNKS / NTHR; j++) {
            int idx = tid + j * NTHR;
            int r = idx >> 2, w = idx & 3;
            const bf16* src;
            if (r < BM)               src = Ahi + (size_t)(m0 + r) * K;
            else if (r < 2 * BM)      src = Alo + (size_t)(m0 + r - BM) * K;
            else if (r < 2 * BM + BN) src = Bhi + (size_t)(n0 + r - 2 * BM) * K;
            else                      src = Blo + (size_t)(n0 + r - 2 * BM - BN) * K;
            cp16(sb + r * 80 + w * 16, src + kblk + w * 8);
        }
    };

    #pragma unroll
    for (int s = 0; s < NS - 1; s++) { load_stage(s, s * 32); cp_commit(); }

    for (int i = 0; i < nc; i++) {
        cp_wait<NS - 2>();
        __syncthreads();
        if (i + NS - 1 < nc) load_stage((i + NS - 1) % NS, (i + NS - 1) * 32);
        cp_commit();

        uint32_t sb = sb0 + (i % NS) * STAGE;
        #pragma unroll
        for (int kst = 0; kst < 2; kst++) {
            uint32_t ah[MT][4], al[MT][4], bh[NTC][2], bl[NTC][2];
            #pragma unroll
            for (int mi = 0; mi < MT; mi++) {
                uint32_t row = warpM * WH + mi * 16 + (lane & 15);
                uint32_t adr = sb + row * 80 + kst * 32 + ((lane >> 4) << 4);
                ldsm4(ah[mi][0], ah[mi][1], ah[mi][2], ah[mi][3], adr);
                ldsm4(al[mi][0], al[mi][1], al[mi][2], al[mi][3], adr + OFF_ALO);
            }
            #pragma unroll
            for (int pr = 0; pr < NTC / 2; pr++) {
                uint32_t row = warpN * WN + pr * 16 + ((lane >> 4) << 3) + (lane & 7);
                uint32_t adr = sb + OFF_BHI + row * 80 + kst * 32 + (((lane >> 3) & 1) << 4);
                ldsm4(bh[2 * pr][0], bh[2 * pr][1], bh[2 * pr + 1][0], bh[2 * pr + 1][1], adr);
                ldsm4(bl[2 * pr][0], bl[2 * pr][1], bl[2 * pr + 1][0], bl[2 * pr + 1][1],
                      adr + BN * 80);
            }
            #pragma unroll
            for (int mi = 0; mi < MT; mi++)
                #pragma unroll
                for (int ni = 0; ni < NTC; ni++) {
                    mma16816(acc[mi][ni], ah[mi], bh[ni]);
                    mma16816(acc[mi][ni], ah[mi], bl[ni]);
                    mma16816(acc[mi][ni], al[mi], bh[ni]);
                }
        }
    }

    // epilogue
    #pragma unroll
    for (int mi = 0; mi < MT; mi++) {
        int r0 = m0 + warpM * WH + mi * 16 + lr;
        const float* bt0 = nullptr; const float* bt1 = nullptr;
        if (BIAS == 1) {
            bt0 = btab + (size_t)action[r0] * N;
            bt1 = btab + (size_t)action[r0 + 8] * N;
        } else if (BIAS == 2) {
            bt0 = btab + (size_t)r0 * ldbias;
            bt1 = btab + (size_t)(r0 + 8) * ldbias;
        }
        #pragma unroll
        for (int ni = 0; ni < NTC; ni++) {
            int c = n0 + warpN * WN + ni * 8 + 2 * lc;
            float v0 = acc[mi][ni][0], v1 = acc[mi][ni][1];
            float v2 = acc[mi][ni][2], v3 = acc[mi][ni][3];
            if (BIAS != 0) { v0 += bt0[c]; v1 += bt0[c + 1]; v2 += bt1[c]; v3 += bt1[c + 1]; }
            if (ACT == 2) {
                // LSTM: even lane has (i,f), odd lane (g,o) of the same j = c>>2.
                float u0 = __shfl_xor_sync(0xffffffffu, v0, 1);
                float u1 = __shfl_xor_sync(0xffffffffu, v1, 1);
                float u2 = __shfl_xor_sync(0xffffffffu, v2, 1);
                float u3 = __shfl_xor_sync(0xffffffffu, v3, 1);
                if ((lc & 1) == 0) {
                    int j = c >> 2;
                    // row r0
                    {
                        float cc = sigmoidf_(v1) * c0_in[(size_t)r0 * HID + j]
                                 + sigmoidf_(v0) * tanhf(u0);
                        float hh = sigmoidf_(u1) * tanhf(cc);
                        c1_out[(size_t)r0 * HID + j] = cc;
                        C[(size_t)r0 * HID + j] = hh;
                        bf16 h, l; split2(hh, h, l);
                        gAh_hi[(size_t)r0 * HID + j] = h;
                        gAh_lo[(size_t)r0 * HID + j] = l;
                    }
                    // row r0+8
                    {
                        int r1 = r0 + 8;
                        float cc = sigmoidf_(v3) * c0_in[(size_t)r1 * HID + j]
                                 + sigmoidf_(v2) * tanhf(u2);
                        float hh = sigmoidf_(u3) * tanhf(cc);
                        c1_out[(size_t)r1 * HID + j] = cc;
                        C[(size_t)r1 * HID + j] = hh;
                        bf16 h, l; split2(hh, h, l);
                        gAh_hi[(size_t)r1 * HID + j] = h;
                        gAh_lo[(size_t)r1 * HID + j] = l;
                    }
                }
            } else {
                if (ACT == 1) { v0 = tanhf(v0); v1 = tanhf(v1); v2 = tanhf(v2); v3 = tanhf(v3); }
                *(float2*)(C + (size_t)r0 * N + c)       = make_float2(v0, v1);
                *(float2*)(C + (size_t)(r0 + 8) * N + c) = make_float2(v2, v3);
            }
        }
    }
}

// ---------------------------------------------------------------------------
// vectorized split helper
// ---------------------------------------------------------------------------
__device__ __forceinline__ void split_chunk8(const float* src, bf16* hid, bf16* lod)
{
    float4 v0 = ((const float4*)src)[0];
    float4 v1 = ((const float4*)src)[1];
    bf16 h[8], l[8];
    split2(v0.x, h[0], l[0]); split2(v0.y, h[1], l[1]);
    split2(v0.z, h[2], l[2]); split2(v0.w, h[3], l[3]);
    split2(v1.x, h[4], l[4]); split2(v1.y, h[5], l[5]);
    split2(v1.z, h[6], l[6]); split2(v1.w, h[7], l[7]);
    *(uint4*)hid = *(uint4*)h;
    *(uint4*)lod = *(uint4*)l;
}

// ---------------------------------------------------------------------------
// MERGED prep kernel. Gates weight rows PERMUTED: perm(n) = (n%HID)*4 + n/HID
// ---------------------------------------------------------------------------
#define GCH   786432   // NGATES*KG/8
#define WINCH 131072   // HID*HID/8
#define WOUTCH 262144  // HID*2*HID/8
#define TOTCH (GCH + WINCH + WOUTCH)   // 1179648
#define NB_W   (TOTCH / 256)           // 4608
#define NB_EMB (NGATES / 8)            // 512
#define NB_GA  ((B * 192) / 256)       // 384
#define NB_ALL (NB_W + NB_EMB + NB_GA + 1)

__global__ __launch_bounds__(256)
void prep_all_kernel(const float* __restrict__ W_ih,
                     const float* __restrict__ W_hh,
                     const float* __restrict__ W_in,
                     const float* __restrict__ W_out,
                     const float* __restrict__ emb,
                     const float* __restrict__ b_ih,
                     const float* __restrict__ b_hh,
                     const float* __restrict__ feature,
                     const float* __restrict__ h0,
                     const unsigned int* __restrict__ maskw)
{
    const int bid = blockIdx.x;
    const int tid = threadIdx.x;

    if (bid < NB_W) {
        int c = bid * 256 + tid;
        if (c < GCH) {
            int n = c / 192, c8 = c % 192;      // n = source row (gate*HID + j)
            const float* src = (c8 < 64) ? W_ih + (size_t)n * (EMB + FEAT) + EMB + c8 * 8
                                         : W_hh + (size_t)n * HID + (size_t)(c8 - 64) * 8;
            int np = (n & (HID - 1)) * 4 + (n >> 10);    // permuted row 4j+gate
            size_t d = (size_t)np * KG + c8 * 8;
            split_chunk8(src, gWg_hi + d, gWg_lo + d);
        } else if (c < GCH + WINCH) {
            size_t d = (size_t)(c - GCH) * 8;
            split_chunk8(W_in + d, gWcat_hi + d, gWcat_lo + d);
        } else {
            size_t e8 = (size_t)(c - GCH - WINCH) * 8;
            int n = (int)(e8 >> 11), col = (int)(e8 & 2047);
            const float* src = W_out + e8;
            if (col < HID) {
                size_t d = (size_t)n * HID + col;
                split_chunk8(src, gWoa_hi + d, gWoa_lo + d);
            } else {
                size_t d = (size_t)(HID + n) * HID + (col - HID);
                split_chunk8(src, gWcat_hi + d, gWcat_lo + d);
            }
        }
    } else if (bid < NB_W + NB_EMB) {
        __shared__ float s_emb[16 * EMB];
        int warp = tid >> 5, lane = tid & 31;
        for (int i = tid; i < 16 * EMB; i += 256) s_emb[i] = emb[i];
        __syncthreads();

        int n = (bid - NB_W) * 8 + warp;        // source row
        int np = (n & (HID - 1)) * 4 + (n >> 10);
        float w[8];
        #pragma unroll
        for (int j = 0; j < 8; j++) w[j] = W_ih[(size_t)n * (EMB + FEAT) + lane + j * 32];
        float bias = b_ih[n] + b_hh[n];
        for (int a = 0; a < 16; a++) {
            float d = 0.f;
            #pragma unroll
            for (int j = 0; j < 8; j++) d += w[j] * s_emb[a * EMB + lane + j * 32];
            #pragma unroll
            for (int o = 16; o; o >>= 1) d += __shfl_xor_sync(0xffffffffu, d, o);
            if (lane == 0) g_embW[a * NGATES + np] = d + bias;
        }
    } else if (bid < NB_W + NB_EMB + NB_GA) {
        int c = (bid - NB_W - NB_EMB) * 256 + tid;
        int b = c / 192, c8 = c % 192;
        const float* src = (c8 < 64) ? feature + (size_t)b * FEAT + c8 * 8
                                     : h0 + (size_t)b * HID + (size_t)(c8 - 64) * 8;
        size_t d = (size_t)b * KG + c8 * 8;
        split_chunk8(src, gAg_hi + d, gAg_lo + d);
    } else {
        int any = 0;
        for (int i = tid; i < 4096; i += 256)
            if (maskw[i] & 0xFFFFFF00u) any = 1;
        any = __syncthreads_or(any);
        if (tid == 0) g_mask_is_u8 = any;
    }
}

// ---------------------------------------------------------------------------
// fused attention — single pass, online softmax, cp.async double-buffered.
// ---------------------------------------------------------------------------
#define ATTN_SMEM ((HID + 2 * 8 * HID + S) * 4)
__global__ __launch_bounds__(256)
void attn_kernel(const float* __restrict__ ctx,
                 const void* __restrict__ mask,
                 float* __restrict__ alpha_out)
{
    extern __shared__ float a_sm[];
    float* s_tgt  = a_sm;                 // 1024
    float* s_tile = a_sm + HID;           // 2 * 8 * 1024
    float* s_attn = a_sm + HID + 16384;   // 256

    const int b = blockIdx.x;
    const int tid = threadIdx.x;
    const int warp = tid >> 5, lane = tid & 31;
    const int mask_u8 = g_mask_is_u8;
    const uint32_t tile_sm = smem_u32(s_tile);

    const unsigned char* mrow_u8 = (const unsigned char*)mask + (size_t)b * S;
    const int*           mrow_i32 = (const int*)mask + (size_t)b * S;
    const char* gbase = (const char*)(ctx + (size_t)b * S * HID);

    {
        const float4* t4 = (const float4*)(g_th + (size_t)b * 2 * HID);
        ((float4*)s_tgt)[tid] = t4[tid];
    }

    auto load_chunk = [&](int buf, int c) {
        uint32_t sb = tile_sm + buf * 32768;
        const char* g = gbase + (size_t)c * 32768;
        #pragma unroll
        for (int j = 0; j < 8; j++) {
            int idx = tid + j * 256;
            cp16(sb + idx * 16, g + idx * 16);
        }
    };

    load_chunk(0, 0); cp_commit();

    float run_max = -1e30f, run_sum = 0.0f;
    float4 facc = make_float4(0.f, 0.f, 0.f, 0.f);

    for (int c = 0; c < S / 8; c++) {
        if (c + 1 < S / 8) { load_chunk((c + 1) & 1, c + 1); cp_commit(); cp_wait<1>(); }
        else               { cp_wait<0>(); }
        __syncthreads();

        const float* tile = s_tile + (c & 1) * 8192;
        const int s0 = c * 8;

        {
            const float* trow = tile + warp * HID;
            float d = 0.f;
            #pragma unroll 8
            for (int i = lane; i < HID; i += 32) d += trow[i] * s_tgt[i];
            #pragma unroll
            for (int o = 16; o; o >>= 1) d += __shfl_xor_sync(0xffffffffu, d, o);
            if (lane == 0) {
                int s = s0 + warp;
                int m = mask_u8 ? (int)mrow_u8[s] : mrow_i32[s];
                if (m) d = -1e30f;
                s_attn[s] = d;
            }
        }
        __syncthreads();

        float cmax = run_max;
        #pragma unroll
        for (int i = 0; i < 8; i++) cmax = fmaxf(cmax, s_attn[s0 + i]);
        float scale = __expf(run_max - cmax);
        run_sum *= scale;
        facc.x *= scale; facc.y *= scale; facc.z *= scale; facc.w *= scale;
        float p[8];
        #pragma unroll
        for (int i = 0; i < 8; i++) { p[i] = __expf(s_attn[s0 + i] - cmax); run_sum += p[i]; }
        run_max = cmax;

        const int dbase = tid * 4;
        #pragma unroll
        for (int i = 0; i < 8; i++) {
            float4 v = *(const float4*)(tile + i * HID + dbase);
            facc.x += p[i] * v.x; facc.y += p[i] * v.y;
            facc.z += p[i] * v.z; facc.w += p[i] * v.w;
        }
        __syncthreads();
    }

    float inv = 1.0f / run_sum;
    size_t oo = (size_t)b * HID + tid * 4;
    float w[4] = { facc.x * inv, facc.y * inv, facc.z * inv, facc.w * inv };
    #pragma unroll
    for (int j = 0; j < 4; j++) {
        bf16 h, l;
        split2(w[j], h, l);
        gAw_hi[oo + j] = h; gAw_lo[oo + j] = l;
    }

    float a = __expf(s_attn[tid] - run_max) * inv;
    alpha_out[(size_t)b * S + tid] = a;
}

// ---------------------------------------------------------------------------
// logit = htilde @ W_dec^T + b_dec
// ---------------------------------------------------------------------------
__global__ void logit_kernel(const float* __restrict__ W_dec,
                             const float* __restrict__ b_dec,
                             float* __restrict__ out)
{
    int b = blockIdx.x;
    int w = threadIdx.x >> 5, lane = threadIdx.x & 31;
    const float* h = g_htilde + (size_t)b * HID;
    const float* wr = W_dec + (size_t)w * HID;
    float s = 0.f;
    #pragma unroll 8
    for (int i = lane; i < HID; i += 32) s += h[i] * wr[i];
    #pragma unroll
    for (int o = 16; o; o >>= 1) s += __shfl_xor_sync(0xffffffffu, s, o);
    if (lane == 0) out[(size_t)b * OUT_ACT + w] = s + b_dec[w];
}

// ---------------------------------------------------------------------------
// launch  (single stream)
// ---------------------------------------------------------------------------
extern "C" void kernel_launch(void* const* d_in, const int* in_sizes, int n_in,
                              void* d_out, int out_size)
{
    const int*   action   = (const int*)d_in[0];
    const float* feature  = (const float*)d_in[1];
    const float* h_0      = (const float*)d_in[2];
    const float* c_0      = (const float*)d_in[3];
    const float* ctx      = (const float*)d_in[4];
    const void*  ctx_mask = d_in[5];
    const float* embedding= (const float*)d_in[6];
    const float* W_ih     = (const float*)d_in[7];
    const float* W_hh     = (const float*)d_in[8];
    const float* b_ih     = (const float*)d_in[9];
    const float* b_hh     = (const float*)d_in[10];
    const float* W_in     = (const float*)d_in[11];
    const float* W_out    = (const float*)d_in[12];
    const float* W_dec    = (const float*)d_in[13];
    const float* b_dec    = (const float*)d_in[14];

    float* out   = (float*)d_out;
    float* h1    = out;
    float* c1    = out + (size_t)B * HID;
    float* alpha = out + (size_t)2 * B * HID;
    float* logit = alpha + (size_t)B * S;

    void* p;
    cudaGetSymbolAddress(&p, g_th);      float* th     = (float*)p;
    cudaGetSymbolAddress(&p, g_htilde);  float* htilde = (float*)p;
    cudaGetSymbolAddress(&p, g_embW);    float* embW   = (float*)p;
    bf16 *ag_hi, *ag_lo, *wg_hi, *wg_lo, *ah_hi, *ah_lo, *aw_hi, *aw_lo;
    bf16 *wcat_hi, *wcat_lo, *woa_hi, *woa_lo;
    cudaGetSymbolAddress(&p, gAg_hi);   ag_hi   = (bf16*)p;
    cudaGetSymbolAddress(&p, gAg_lo);   ag_lo   = (bf16*)p;
    cudaGetSymbolAddress(&p, gWg_hi);   wg_hi   = (bf16*)p;
    cudaGetSymbolAddress(&p, gWg_lo);   wg_lo   = (bf16*)p;
    cudaGetSymbolAddress(&p, gAh_hi);   ah_hi   = (bf16*)p;
    cudaGetSymbolAddress(&p, gAh_lo);   ah_lo   = (bf16*)p;
    cudaGetSymbolAddress(&p, gAw_hi);   aw_hi   = (bf16*)p;
    cudaGetSymbolAddress(&p, gAw_lo);   aw_lo   = (bf16*)p;
    cudaGetSymbolAddress(&p, gWcat_hi); wcat_hi = (bf16*)p;
    cudaGetSymbolAddress(&p, gWcat_lo); wcat_lo = (bf16*)p;
    cudaGetSymbolAddress(&p, gWoa_hi);  woa_hi  = (bf16*)p;
    cudaGetSymbolAddress(&p, gWoa_lo);  woa_lo  = (bf16*)p;

    const int SMEM_GATES = 2 * (2 * 128 + 2 * 64) * 80;    // 61440
    const int SMEM_6464  = 3 * (2 * 64 + 2 * 64) * 80;     // 61440
    const int SMEM_SMALL = 3 * (2 * 64 + 2 * 32) * 80;     // 46080
    static bool attr_done = false;
    if (!attr_done) {
        cudaFuncSetAttribute((const void*)tc_gemm<128, 64, 4, 4, 2, 512, 1, 2>,
                             cudaFuncAttributeMaxDynamicSharedMemorySize, SMEM_GATES);
        cudaFuncSetAttribute((const void*)tc_gemm<64, 64, 2, 4, 3, 256, 0, 0>,
                             cudaFuncAttributeMaxDynamicSharedMemorySize, SMEM_6464);
        cudaFuncSetAttribute((const void*)tc_gemm<64, 32, 4, 2, 3, 256, 2, 1>,
                             cudaFuncAttributeMaxDynamicSharedMemorySize, SMEM_SMALL);
        cudaFuncSetAttribute((const void*)attn_kernel,
                             cudaFuncAttributeMaxDynamicSharedMemorySize, ATTN_SMEM);
        attr_done = true;
    }

    // 0: all prep in ONE launch (permuted gates weights)
    prep_all_kernel<<<NB_ALL, 256>>>(W_ih, W_hh, W_in, W_out, embedding,
                                     b_ih, b_hh, feature, h_0,
                                     (const unsigned int*)ctx_mask);

    // 1: gates GEMM with fused LSTM epilogue -> h1, c1, gAh splits
    tc_gemm<128, 64, 4, 4, 2, 512, 1, 2><<<dim3(NGATES / 64, B / 128), 512, SMEM_GATES>>>(
        ag_hi, ag_lo, wg_hi, wg_lo, action, embW, 0, c_0, c1, h1, NGATES, KG);

    // 2: fused [target | half2] = h1 @ [W_in ; W_out[:,1024:]]^T  (64x64 tiles, 256 CTAs)
    tc_gemm<64, 64, 2, 4, 3, 256, 0, 0><<<dim3(2 * HID / 64, B / 64), 256, SMEM_6464>>>(
        ah_hi, ah_lo, wcat_hi, wcat_lo, nullptr, nullptr, 0, nullptr, nullptr,
        th, 2 * HID, HID);

    // 3: fused attention -> alpha, weighted(split)
    attn_kernel<<<B, 256, ATTN_SMEM>>>(ctx, ctx_mask, alpha);

    // 4: htilde = tanh(weighted @ W_out[:, :1024]^T + half2)
    tc_gemm<64, 32, 4, 2, 3, 256, 2, 1><<<dim3(HID / 32, B / 64), 256, SMEM_SMALL>>>(
        aw_hi, aw_lo, woa_hi, woa_lo, nullptr, th + HID, 2 * HID, nullptr, nullptr,
        htilde, HID, HID);

    // 5: logit
    logit_kernel<<<B, OUT_ACT * 32>>>(W_dec, b_dec, logit);
}

// round 15
// speedup vs baseline: 1.0993x; 1.0993x over previous
#include <cuda_runtime.h>
#include <cuda_bf16.h>
#include <cstdint>

// Shapes (fixed)
#define B 512
#define S 256
#define EMB 256
#define FEAT 512
#define HID 1024
#define OUT_ACT 14
#define KG 1536                    // gates GEMM K after emb fold: FEAT + HID
#define NGATES 4096

typedef __nv_bfloat16 bf16;

// ---------------------------------------------------------------------------
// Scratch (device globals; no allocation allowed)
// ---------------------------------------------------------------------------
__device__ float g_gates[B * NGATES];
__device__ float g_th[B * 2 * HID];      // [target | half2]  (fused GEMM output)
__device__ float g_htilde[B * HID];
__device__ float g_embW[16 * NGATES];    // emb@W_ih[:, :256]^T + b_ih + b_hh
__device__ int   g_mask_is_u8;

// attention split-KV partials
__device__ float g_pm[B * 2];            // partial max
__device__ float g_ps[B * 2];            // partial sum (unnormalized)
__device__ float g_pfacc[B * 2 * HID];   // partial weighted acc (unnormalized)
__device__ float g_scores[B * S];        // masked raw scores

// bf16 hi/lo split buffers
__device__ bf16 gAg_hi[B * KG],         gAg_lo[B * KG];           // [feature|h0]
__device__ bf16 gWg_hi[NGATES * KG],    gWg_lo[NGATES * KG];      // [W_ih[:,256:]|W_hh]
__device__ bf16 gAh_hi[B * HID],        gAh_lo[B * HID];          // h1
__device__ bf16 gAw_hi[B * HID],        gAw_lo[B * HID];          // weighted
__device__ bf16 gWcat_hi[2 * HID * HID], gWcat_lo[2 * HID * HID]; // [W_in ; W_out[:,1024:]]
__device__ bf16 gWoa_hi[HID * HID],     gWoa_lo[HID * HID];       // W_out[:, :1024]

__device__ __forceinline__ float sigmoidf_(float x) { return 1.0f / (1.0f + expf(-x)); }

__device__ __forceinline__ void split2(float v, bf16& h, bf16& l) {
    h = __float2bfloat16(v);
    l = __float2bfloat16(v - __bfloat162float(h));
}

// ---------------------------------------------------------------------------
// PTX helpers
// ---------------------------------------------------------------------------
__device__ __forceinline__ uint32_t smem_u32(const void* p) {
    uint32_t a;
    asm("{ .reg .u64 t; cvta.to.shared.u64 t, %1; cvt.u32.u64 %0, t; }" : "=r"(a) : "l"(p));
    return a;
}
__device__ __forceinline__ void cp16(uint32_t saddr, const void* g) {
    asm volatile("cp.async.cg.shared.global [%0], [%1], 16;\n" :: "r"(saddr), "l"(g));
}
__device__ __forceinline__ void cp_commit() { asm volatile("cp.async.commit_group;\n" ::: "memory"); }
template <int N>
__device__ __forceinline__ void cp_wait() { asm volatile("cp.async.wait_group %0;\n" :: "n"(N) : "memory"); }

__device__ __forceinline__ void ldsm4(uint32_t& r0, uint32_t& r1, uint32_t& r2, uint32_t& r3,
                                      uint32_t addr) {
    asm volatile("ldmatrix.sync.aligned.m8n8.x4.shared.b16 {%0,%1,%2,%3}, [%4];"
        : "=r"(r0), "=r"(r1), "=r"(r2), "=r"(r3) : "r"(addr));
}
__device__ __forceinline__ void mma16816(float* c, const uint32_t* a, const uint32_t* b) {
    asm volatile(
        "mma.sync.aligned.m16n8k16.row.col.f32.bf16.bf16.f32 "
        "{%0,%1,%2,%3},{%4,%5,%6,%7},{%8,%9},{%0,%1,%2,%3};"
        : "+f"(c[0]), "+f"(c[1]), "+f"(c[2]), "+f"(c[3])
        : "r"(a[0]), "r"(a[1]), "r"(a[2]), "r"(a[3]), "r"(b[0]), "r"(b[1]));
}

// ---------------------------------------------------------------------------
// split-bf16 GEMM (mma.sync + ldmatrix + NS-stage cp.async)
// BIAS: 0 none, 1 action table btab[action[row]][col] (stride N),
//       2 elementwise btab[row*ldbias + col].  ACT: 0 none, 1 tanh.
// ---------------------------------------------------------------------------
template <int BM, int BN, int WGM, int WGN, int NS, int NTHR, int BIAS, int ACT>
__global__ __launch_bounds__(NTHR)
void tc_gemm(const bf16* __restrict__ Ahi, const bf16* __restrict__ Alo,
             const bf16* __restrict__ Bhi, const bf16* __restrict__ Blo,
             const int* __restrict__ action, const float* __restrict__ btab,
             int ldbias, float* __restrict__ C, int N, int K)
{
    constexpr int WH  = BM / WGM, WN = BN / WGN;
    constexpr int MT  = WH / 16,  NTC = WN / 8;
    constexpr int STAGE   = (2 * BM + 2 * BN) * 80;
    constexpr int OFF_ALO = BM * 80;
    constexpr int OFF_BHI = 2 * BM * 80;
    constexpr int ROWS    = 2 * BM + 2 * BN;
    constexpr int CHUNKS  = ROWS * 4;          // 16B chunks per stage

    extern __shared__ char sm[];
    const int tid  = threadIdx.x;
    const int warp = tid >> 5, lane = tid & 31;
    const int warpM = warp / WGN, warpN = warp % WGN;
    const int lr = lane >> 2, lc = lane & 3;
    const int m0 = blockIdx.y * BM;
    const int n0 = blockIdx.x * BN;
    const uint32_t sb0 = smem_u32(sm);

    float acc[MT][NTC][4] = {};

    const int nc = K >> 5;    // BK=32

    auto load_stage = [&](int buf, int kblk) {
        uint32_t sb = sb0 + buf * STAGE;
        #pragma unroll
        for (int j = 0; j < CHUNKS / NTHR; j++) {
            int idx = tid + j * NTHR;
            int r = idx >> 2, w = idx & 3;
            const bf16* src;
            if (r < BM)               src = Ahi + (size_t)(m0 + r) * K;
            else if (r < 2 * BM)      src = Alo + (size_t)(m0 + r - BM) * K;
            else if (r < 2 * BM + BN) src = Bhi + (size_t)(n0 + r - 2 * BM) * K;
            else                      src = Blo + (size_t)(n0 + r - 2 * BM - BN) * K;
            cp16(sb + r * 80 + w * 16, src + kblk + w * 8);
        }
    };

    #pragma unroll
    for (int s = 0; s < NS - 1; s++) { load_stage(s, s * 32); cp_commit(); }

    for (int i = 0; i < nc; i++) {
        cp_wait<NS - 2>();
        __syncthreads();
        if (i + NS - 1 < nc) load_stage((i + NS - 1) % NS, (i + NS - 1) * 32);
        cp_commit();

        uint32_t sb = sb0 + (i % NS) * STAGE;
        #pragma unroll
        for (int kst = 0; kst < 2; kst++) {
            uint32_t ah[MT][4], al[MT][4], bh[NTC][2], bl[NTC][2];
            #pragma unroll
            for (int mi = 0; mi < MT; mi++) {
                uint32_t row = warpM * WH + mi * 16 + (lane & 15);
                uint32_t adr = sb + row * 80 + kst * 32 + ((lane >> 4) << 4);
                ldsm4(ah[mi][0], ah[mi][1], ah[mi][2], ah[mi][3], adr);
                ldsm4(al[mi][0], al[mi][1], al[mi][2], al[mi][3], adr + OFF_ALO);
            }
            #pragma unroll
            for (int pr = 0; pr < NTC / 2; pr++) {
                uint32_t row = warpN * WN + pr * 16 + ((lane >> 4) << 3) + (lane & 7);
                uint32_t adr = sb + OFF_BHI + row * 80 + kst * 32 + (((lane >> 3) & 1) << 4);
                ldsm4(bh[2 * pr][0], bh[2 * pr][1], bh[2 * pr + 1][0], bh[2 * pr + 1][1], adr);
                ldsm4(bl[2 * pr][0], bl[2 * pr][1], bl[2 * pr + 1][0], bl[2 * pr + 1][1],
                      adr + BN * 80);
            }
            #pragma unroll
            for (int mi = 0; mi < MT; mi++)
                #pragma unroll
                for (int ni = 0; ni < NTC; ni++) {
                    mma16816(acc[mi][ni], ah[mi], bh[ni]);
                    mma16816(acc[mi][ni], ah[mi], bl[ni]);
                    mma16816(acc[mi][ni], al[mi], bh[ni]);
                }
        }
    }

    // epilogue
    #pragma unroll
    for (int mi = 0; mi < MT; mi++) {
        int r0 = m0 + warpM * WH + mi * 16 + lr;
        const float* bt0 = nullptr; const float* bt1 = nullptr;
        if (BIAS == 1) {
            bt0 = btab + (size_t)action[r0] * N;
            bt1 = btab + (size_t)action[r0 + 8] * N;
        } else if (BIAS == 2) {
            bt0 = btab + (size_t)r0 * ldbias;
            bt1 = btab + (size_t)(r0 + 8) * ldbias;
        }
        #pragma unroll
        for (int ni = 0; ni < NTC; ni++) {
            int c = n0 + warpN * WN + ni * 8 + 2 * lc;
            float v0 = acc[mi][ni][0], v1 = acc[mi][ni][1];
            float v2 = acc[mi][ni][2], v3 = acc[mi][ni][3];
            if (BIAS != 0) { v0 += bt0[c]; v1 += bt0[c + 1]; v2 += bt1[c]; v3 += bt1[c + 1]; }
            if (ACT == 1)  { v0 = tanhf(v0); v1 = tanhf(v1); v2 = tanhf(v2); v3 = tanhf(v3); }
            *(float2*)(C + (size_t)r0 * N + c)       = make_float2(v0, v1);
            *(float2*)(C + (size_t)(r0 + 8) * N + c) = make_float2(v2, v3);
        }
    }
}

// ---------------------------------------------------------------------------
// vectorized split helper
// ---------------------------------------------------------------------------
__device__ __forceinline__ void split_chunk8(const float* src, bf16* hid, bf16* lod)
{
    float4 v0 = ((const float4*)src)[0];
    float4 v1 = ((const float4*)src)[1];
    bf16 h[8], l[8];
    split2(v0.x, h[0], l[0]); split2(v0.y, h[1], l[1]);
    split2(v0.z, h[2], l[2]); split2(v0.w, h[3], l[3]);
    split2(v1.x, h[4], l[4]); split2(v1.y, h[5], l[5]);
    split2(v1.z, h[6], l[6]); split2(v1.w, h[7], l[7]);
    *(uint4*)hid = *(uint4*)h;
    *(uint4*)lod = *(uint4*)l;
}

// ---------------------------------------------------------------------------
// MERGED prep kernel (one launch, blockIdx-partitioned; parts independent)
// ---------------------------------------------------------------------------
#define GCH   786432   // NGATES*KG/8
#define WINCH 131072   // HID*HID/8
#define WOUTCH 262144  // HID*2*HID/8
#define TOTCH (GCH + WINCH + WOUTCH)   // 1179648
#define NB_W   (TOTCH / 256)           // 4608
#define NB_EMB (NGATES / 8)            // 512
#define NB_GA  ((B * 192) / 256)       // 384
#define NB_ALL (NB_W + NB_EMB + NB_GA + 1)

__global__ __launch_bounds__(256)
void prep_all_kernel(const float* __restrict__ W_ih,
                     const float* __restrict__ W_hh,
                     const float* __restrict__ W_in,
                     const float* __restrict__ W_out,
                     const float* __restrict__ emb,
                     const float* __restrict__ b_ih,
                     const float* __restrict__ b_hh,
                     const float* __restrict__ feature,
                     const float* __restrict__ h0,
                     const unsigned int* __restrict__ maskw)
{
    const int bid = blockIdx.x;
    const int tid = threadIdx.x;

    if (bid < NB_W) {
        int c = bid * 256 + tid;
        if (c < GCH) {
            int n = c / 192, c8 = c % 192;
            const float* src = (c8 < 64) ? W_ih + (size_t)n * (EMB + FEAT) + EMB + c8 * 8
                                         : W_hh + (size_t)n * HID + (size_t)(c8 - 64) * 8;
            size_t d = (size_t)n * KG + c8 * 8;
            split_chunk8(src, gWg_hi + d, gWg_lo + d);
        } else if (c < GCH + WINCH) {
            size_t d = (size_t)(c - GCH) * 8;       // W_in -> Wcat rows [0,1024)
            split_chunk8(W_in + d, gWcat_hi + d, gWcat_lo + d);
        } else {
            size_t e8 = (size_t)(c - GCH - WINCH) * 8;   // offset in W_out [1024 x 2048]
            int n = (int)(e8 >> 11), col = (int)(e8 & 2047);
            const float* src = W_out + e8;
            if (col < HID) {
                size_t d = (size_t)n * HID + col;
                split_chunk8(src, gWoa_hi + d, gWoa_lo + d);
            } else {
                size_t d = (size_t)(HID + n) * HID + (col - HID);
                split_chunk8(src, gWcat_hi + d, gWcat_lo + d);
            }
        }
    } else if (bid < NB_W + NB_EMB) {
        __shared__ float s_emb[16 * EMB];
        int warp = tid >> 5, lane = tid & 31;
        for (int i = tid; i < 16 * EMB; i += 256) s_emb[i] = emb[i];
        __syncthreads();

        int n = (bid - NB_W) * 8 + warp;
        float w[8];
        #pragma unroll
        for (int j = 0; j < 8; j++) w[j] = W_ih[(size_t)n * (EMB + FEAT) + lane + j * 32];
        float bias = b_ih[n] + b_hh[n];
        for (int a = 0; a < 16; a++) {
            float d = 0.f;
            #pragma unroll
            for (int j = 0; j < 8; j++) d += w[j] * s_emb[a * EMB + lane + j * 32];
            #pragma unroll
            for (int o = 16; o; o >>= 1) d += __shfl_xor_sync(0xffffffffu, d, o);
            if (lane == 0) g_embW[a * NGATES + n] = d + bias;
        }
    } else if (bid < NB_W + NB_EMB + NB_GA) {
        int c = (bid - NB_W - NB_EMB) * 256 + tid;
        int b = c / 192, c8 = c % 192;
        const float* src = (c8 < 64) ? feature + (size_t)b * FEAT + c8 * 8
                                     : h0 + (size_t)b * HID + (size_t)(c8 - 64) * 8;
        size_t d = (size_t)b * KG + c8 * 8;
        split_chunk8(src, gAg_hi + d, gAg_lo + d);
    } else {
        int any = 0;
        for (int i = tid; i < 4096; i += 256)
            if (maskw[i] & 0xFFFFFF00u) any = 1;
        any = __syncthreads_or(any);
        if (tid == 0) g_mask_is_u8 = any;
    }
}

// ---------------------------------------------------------------------------
// LSTM elementwise; writes h1 splits (gAh) for the fused target|half2 GEMM
// ---------------------------------------------------------------------------
__global__ void lstm_cell_kernel(const float* __restrict__ c0,
                                 float* __restrict__ h1_out,
                                 float* __restrict__ c1_out)
{
    int idx = blockIdx.x * blockDim.x + threadIdx.x;   // B*HID
    int b = idx >> 10, j = idx & 1023;
    const float* g = g_gates + (size_t)b * NGATES;
    float gi = g[j];
    float gf = g[HID + j];
    float gg = g[2 * HID + j];
    float go = g[3 * HID + j];
    float c1 = sigmoidf_(gf) * c0[idx] + sigmoidf_(gi) * tanhf(gg);
    float h1 = sigmoidf_(go) * tanhf(c1);
    c1_out[idx] = c1;
    h1_out[idx] = h1;
    bf16 h, l;
    split2(h1, h, l);
    gAh_hi[idx] = h; gAh_lo[idx] = l;
}

// ---------------------------------------------------------------------------
// split-KV attention part: each CTA handles 128 seq positions of one batch row.
// grid (B, 2). Writes unnormalized partials + masked raw scores.
// smem: s_tgt[1024] | s_tile[2][8][1024] | s_attn[128]
// ---------------------------------------------------------------------------
#define ATTNP_SMEM ((HID + 2 * 8 * HID + 128) * 4)
__global__ __launch_bounds__(256)
void attn_part_kernel(const float* __restrict__ ctx, const void* __restrict__ mask)
{
    extern __shared__ float a_sm[];
    float* s_tgt  = a_sm;                 // 1024
    float* s_tile = a_sm + HID;           // 2 * 8 * 1024
    float* s_attn = a_sm + HID + 16384;   // 128

    const int b = blockIdx.x;
    const int half = blockIdx.y;
    const int tid = threadIdx.x;
    const int warp = tid >> 5, lane = tid & 31;
    const int mask_u8 = g_mask_is_u8;
    const uint32_t tile_sm = smem_u32(s_tile);

    const unsigned char* mrow_u8 = (const unsigned char*)mask + (size_t)b * S + half * 128;
    const int*           mrow_i32 = (const int*)mask + (size_t)b * S + half * 128;
    const char* gbase = (const char*)(ctx + (size_t)b * S * HID + (size_t)half * 128 * HID);

    {
        const float4* t4 = (const float4*)(g_th + (size_t)b * 2 * HID);
        ((float4*)s_tgt)[tid] = t4[tid];
    }

    auto load_chunk = [&](int buf, int c) {
        uint32_t sb = tile_sm + buf * 32768;
        const char* g = gbase + (size_t)c * 32768;
        #pragma unroll
        for (int j = 0; j < 8; j++) {
            int idx = tid + j * 256;
            cp16(sb + idx * 16, g + idx * 16);
        }
    };

    load_chunk(0, 0); cp_commit();

    float run_max = -1e30f, run_sum = 0.0f;
    float4 facc = make_float4(0.f, 0.f, 0.f, 0.f);
    const int NC = 16;   // 128 positions / 8

    for (int c = 0; c < NC; c++) {
        if (c + 1 < NC) { load_chunk((c + 1) & 1, c + 1); cp_commit(); cp_wait<1>(); }
        else            { cp_wait<0>(); }
        __syncthreads();

        const float* tile = s_tile + (c & 1) * 8192;
        const int s0 = c * 8;

        {
            const float* trow = tile + warp * HID;
            float d = 0.f;
            #pragma unroll 8
            for (int i = lane; i < HID; i += 32) d += trow[i] * s_tgt[i];
            #pragma unroll
            for (int o = 16; o; o >>= 1) d += __shfl_xor_sync(0xffffffffu, d, o);
            if (lane == 0) {
                int s = s0 + warp;
                int m = mask_u8 ? (int)mrow_u8[s] : mrow_i32[s];
                if (m) d = -1e30f;
                s_attn[s] = d;
            }
        }
        __syncthreads();

        float cmax = run_max;
        #pragma unroll
        for (int i = 0; i < 8; i++) cmax = fmaxf(cmax, s_attn[s0 + i]);
        float scale = __expf(run_max - cmax);
        run_sum *= scale;
        facc.x *= scale; facc.y *= scale; facc.z *= scale; facc.w *= scale;
        float p[8];
        #pragma unroll
        for (int i = 0; i < 8; i++) { p[i] = __expf(s_attn[s0 + i] - cmax); run_sum += p[i]; }
        run_max = cmax;

        const int dbase = tid * 4;
        #pragma unroll
        for (int i = 0; i < 8; i++) {
            float4 v = *(const float4*)(tile + i * HID + dbase);
            facc.x += p[i] * v.x; facc.y += p[i] * v.y;
            facc.z += p[i] * v.z; facc.w += p[i] * v.w;
        }
        __syncthreads();
    }

    const int pi = b * 2 + half;
    if (tid == 0) { g_pm[pi] = run_max; g_ps[pi] = run_sum; }
    *(float4*)(g_pfacc + (size_t)pi * HID + tid * 4) = facc;
    if (tid < 128) g_scores[(size_t)b * S + half * 128 + tid] = s_attn[tid];
}

// ---------------------------------------------------------------------------
// attention combine: merge 2 partials per batch row; write alpha + gAw splits.
// ---------------------------------------------------------------------------
__global__ __launch_bounds__(256)
void attn_combine_kernel(float* __restrict__ alpha_out)
{
    const int b = blockIdx.x, tid = threadIdx.x;
    float m0 = g_pm[b * 2], m1 = g_pm[b * 2 + 1];
    float s0 = g_ps[b * 2], s1 = g_ps[b * 2 + 1];
    float m = fmaxf(m0, m1);
    float e0 = __expf(m0 - m), e1 = __expf(m1 - m);
    float inv = 1.0f / (s0 * e0 + s1 * e1);

    float4 f0 = *(const float4*)(g_pfacc + (size_t)(b * 2) * HID + tid * 4);
    float4 f1 = *(const float4*)(g_pfacc + (size_t)(b * 2 + 1) * HID + tid * 4);
    float w[4] = { (f0.x * e0 + f1.x * e1) * inv, (f0.y * e0 + f1.y * e1) * inv,
                   (f0.z * e0 + f1.z * e1) * inv, (f0.w * e0 + f1.w * e1) * inv };
    size_t oo = (size_t)b * HID + tid * 4;
    #pragma unroll
    for (int j = 0; j < 4; j++) {
        bf16 h, l;
        split2(w[j], h, l);
        gAw_hi[oo + j] = h; gAw_lo[oo + j] = l;
    }

    float a = __expf(g_scores[(size_t)b * S + tid] - m) * inv;
    alpha_out[(size_t)b * S + tid] = a;
}

// ---------------------------------------------------------------------------
// logit = htilde @ W_dec^T + b_dec
// ---------------------------------------------------------------------------
__global__ void logit_kernel(const float* __restrict__ W_dec,
                             const float* __restrict__ b_dec,
                             float* __restrict__ out)
{
    int b = blockIdx.x;
    int w = threadIdx.x >> 5, lane = threadIdx.x & 31;
    const float* h = g_htilde + (size_t)b * HID;
    const float* wr = W_dec + (size_t)w * HID;
    float s = 0.f;
    #pragma unroll 8
    for (int i = lane; i < HID; i += 32) s += h[i] * wr[i];
    #pragma unroll
    for (int o = 16; o; o >>= 1) s += __shfl_xor_sync(0xffffffffu, s, o);
    if (lane == 0) out[(size_t)b * OUT_ACT + w] = s + b_dec[w];
}

// ---------------------------------------------------------------------------
// launch  (single stream)
// ---------------------------------------------------------------------------
extern "C" void kernel_launch(void* const* d_in, const int* in_sizes, int n_in,
                              void* d_out, int out_size)
{
    const int*   action   = (const int*)d_in[0];
    const float* feature  = (const float*)d_in[1];
    const float* h_0      = (const float*)d_in[2];
    const float* c_0      = (const float*)d_in[3];
    const float* ctx      = (const float*)d_in[4];
    const void*  ctx_mask = d_in[5];
    const float* embedding= (const float*)d_in[6];
    const float* W_ih     = (const float*)d_in[7];
    const float* W_hh     = (const float*)d_in[8];
    const float* b_ih     = (const float*)d_in[9];
    const float* b_hh     = (const float*)d_in[10];
    const float* W_in     = (const float*)d_in[11];
    const float* W_out    = (const float*)d_in[12];
    const float* W_dec    = (const float*)d_in[13];
    const float* b_dec    = (const float*)d_in[14];

    float* out   = (float*)d_out;
    float* h1    = out;
    float* c1    = out + (size_t)B * HID;
    float* alpha = out + (size_t)2 * B * HID;
    float* logit = alpha + (size_t)B * S;

    void* p;
    cudaGetSymbolAddress(&p, g_gates);   float* gates  = (float*)p;
    cudaGetSymbolAddress(&p, g_th);      float* th     = (float*)p;
    cudaGetSymbolAddress(&p, g_htilde);  float* htilde = (float*)p;
    cudaGetSymbolAddress(&p, g_embW);    float* embW   = (float*)p;
    bf16 *ag_hi, *ag_lo, *wg_hi, *wg_lo, *ah_hi, *ah_lo, *aw_hi, *aw_lo;
    bf16 *wcat_hi, *wcat_lo, *woa_hi, *woa_lo;
    cudaGetSymbolAddress(&p, gAg_hi);   ag_hi   = (bf16*)p;
    cudaGetSymbolAddress(&p, gAg_lo);   ag_lo   = (bf16*)p;
    cudaGetSymbolAddress(&p, gWg_hi);   wg_hi   = (bf16*)p;
    cudaGetSymbolAddress(&p, gWg_lo);   wg_lo   = (bf16*)p;
    cudaGetSymbolAddress(&p, gAh_hi);   ah_hi   = (bf16*)p;
    cudaGetSymbolAddress(&p, gAh_lo);   ah_lo   = (bf16*)p;
    cudaGetSymbolAddress(&p, gAw_hi);   aw_hi   = (bf16*)p;
    cudaGetSymbolAddress(&p, gAw_lo);   aw_lo   = (bf16*)p;
    cudaGetSymbolAddress(&p, gWcat_hi); wcat_hi = (bf16*)p;
    cudaGetSymbolAddress(&p, gWcat_lo); wcat_lo = (bf16*)p;
    cudaGetSymbolAddress(&p, gWoa_hi);  woa_hi  = (bf16*)p;
    cudaGetSymbolAddress(&p, gWoa_lo);  woa_lo  = (bf16*)p;

    const int SMEM_GATES = 2 * (2 * 128 + 2 * 64) * 80;    // 61440
    const int SMEM_6464  = 3 * (2 * 64 + 2 * 64) * 80;     // 61440
    const int SMEM_SMALL = 3 * (2 * 64 + 2 * 32) * 80;     // 46080
    static bool attr_done = false;
    if (!attr_done) {
        cudaFuncSetAttribute((const void*)tc_gemm<128, 64, 4, 4, 2, 512, 1, 0>,
                             cudaFuncAttributeMaxDynamicSharedMemorySize, SMEM_GATES);
        cudaFuncSetAttribute((const void*)tc_gemm<64, 64, 2, 4, 3, 256, 0, 0>,
                             cudaFuncAttributeMaxDynamicSharedMemorySize, SMEM_6464);
        cudaFuncSetAttribute((const void*)tc_gemm<64, 32, 4, 2, 3, 256, 2, 1>,
                             cudaFuncAttributeMaxDynamicSharedMemorySize, SMEM_SMALL);
        cudaFuncSetAttribute((const void*)attn_part_kernel,
                             cudaFuncAttributeMaxDynamicSharedMemorySize, ATTNP_SMEM);
        attr_done = true;
    }

    // 0: all prep in ONE launch
    prep_all_kernel<<<NB_ALL, 256>>>(W_ih, W_hh, W_in, W_out, embedding,
                                     b_ih, b_hh, feature, h_0,
                                     (const unsigned int*)ctx_mask);

    // 1: gates GEMM — champion config
    tc_gemm<128, 64, 4, 4, 2, 512, 1, 0><<<dim3(NGATES / 64, B / 128), 512, SMEM_GATES>>>(
        ag_hi, ag_lo, wg_hi, wg_lo, action, embW, 0, gates, NGATES, KG);

    // 2: LSTM elementwise -> h1, c1 (+ h1 splits)
    lstm_cell_kernel<<<(B * HID) / 256, 256>>>(c_0, h1, c1);

    // 3: fused [target | half2] = h1 @ [W_in ; W_out[:,1024:]]^T  (64x64 tiles)
    tc_gemm<64, 64, 2, 4, 3, 256, 0, 0><<<dim3(2 * HID / 64, B / 64), 256, SMEM_6464>>>(
        ah_hi, ah_lo, wcat_hi, wcat_lo, nullptr, nullptr, 0, th, 2 * HID, HID);

    // 4: split-KV attention parts (grid B x 2)
    attn_part_kernel<<<dim3(B, 2), 256, ATTNP_SMEM>>>(ctx, ctx_mask);

    // 5: combine partials -> alpha, weighted(split)
    attn_combine_kernel<<<B, 256>>>(alpha);

    // 6: htilde = tanh(weighted @ W_out[:, :1024]^T + half2)
    tc_gemm<64, 32, 4, 2, 3, 256, 2, 1><<<dim3(HID / 32, B / 64), 256, SMEM_SMALL>>>(
        aw_hi, aw_lo, woa_hi, woa_lo, nullptr, th + HID, 2 * HID, htilde, HID, HID);

    // 7: logit
    logit_kernel<<<B, OUT_ACT * 32>>>(W_dec, b_dec, logit);
}

// round 16
// speedup vs baseline: 1.1281x; 1.0263x over previous
#include <cuda_runtime.h>
#include <cuda_bf16.h>
#include <cstdint>

// Shapes (fixed)
#define B 512
#define S 256
#define EMB 256
#define FEAT 512
#define HID 1024
#define OUT_ACT 14
#define KG 1536                    // gates GEMM K after emb fold: FEAT + HID
#define NGATES 4096
#define NPART 4                    // attention split-KV parts
#define PPOS (S / NPART)           // 64 positions per part

typedef __nv_bfloat16 bf16;

// ---------------------------------------------------------------------------
// Scratch (device globals; no allocation allowed)
// ---------------------------------------------------------------------------
__device__ float g_gates[B * NGATES];
__device__ float g_th[B * 2 * HID];      // [target | half2]  (fused GEMM output)
__device__ float g_htilde[B * HID];
__device__ float g_embW[16 * NGATES];    // emb@W_ih[:, :256]^T + b_ih + b_hh
__device__ int   g_mask_is_u8;

// attention split-KV partials
__device__ float g_pm[B * NPART];            // partial max
__device__ float g_ps[B * NPART];            // partial sum (unnormalized)
__device__ float g_pfacc[B * NPART * HID];   // partial weighted acc (unnormalized)
__device__ float g_scores[B * S];            // masked raw scores

// bf16 hi/lo split buffers
__device__ bf16 gAg_hi[B * KG],         gAg_lo[B * KG];           // [feature|h0]
__device__ bf16 gWg_hi[NGATES * KG],    gWg_lo[NGATES * KG];      // [W_ih[:,256:]|W_hh]
__device__ bf16 gAh_hi[B * HID],        gAh_lo[B * HID];          // h1
__device__ bf16 gAw_hi[B * HID],        gAw_lo[B * HID];          // weighted
__device__ bf16 gWcat_hi[2 * HID * HID], gWcat_lo[2 * HID * HID]; // [W_in ; W_out[:,1024:]]
__device__ bf16 gWoa_hi[HID * HID],     gWoa_lo[HID * HID];       // W_out[:, :1024]

__device__ __forceinline__ float sigmoidf_(float x) { return 1.0f / (1.0f + expf(-x)); }

__device__ __forceinline__ void split2(float v, bf16& h, bf16& l) {
    h = __float2bfloat16(v);
    l = __float2bfloat16(v - __bfloat162float(h));
}

// ---------------------------------------------------------------------------
// PTX helpers
// ---------------------------------------------------------------------------
__device__ __forceinline__ uint32_t smem_u32(const void* p) {
    uint32_t a;
    asm("{ .reg .u64 t; cvta.to.shared.u64 t, %1; cvt.u32.u64 %0, t; }" : "=r"(a) : "l"(p));
    return a;
}
__device__ __forceinline__ void cp16(uint32_t saddr, const void* g) {
    asm volatile("cp.async.cg.shared.global [%0], [%1], 16;\n" :: "r"(saddr), "l"(g));
}
__device__ __forceinline__ void cp_commit() { asm volatile("cp.async.commit_group;\n" ::: "memory"); }
template <int N>
__device__ __forceinline__ void cp_wait() { asm volatile("cp.async.wait_group %0;\n" :: "n"(N) : "memory"); }

__device__ __forceinline__ void ldsm4(uint32_t& r0, uint32_t& r1, uint32_t& r2, uint32_t& r3,
                                      uint32_t addr) {
    asm volatile("ldmatrix.sync.aligned.m8n8.x4.shared.b16 {%0,%1,%2,%3}, [%4];"
        : "=r"(r0), "=r"(r1), "=r"(r2), "=r"(r3) : "r"(addr));
}
__device__ __forceinline__ void mma16816(float* c, const uint32_t* a, const uint32_t* b) {
    asm volatile(
        "mma.sync.aligned.m16n8k16.row.col.f32.bf16.bf16.f32 "
        "{%0,%1,%2,%3},{%4,%5,%6,%7},{%8,%9},{%0,%1,%2,%3};"
        : "+f"(c[0]), "+f"(c[1]), "+f"(c[2]), "+f"(c[3])
        : "r"(a[0]), "r"(a[1]), "r"(a[2]), "r"(a[3]), "r"(b[0]), "r"(b[1]));
}

// ---------------------------------------------------------------------------
// split-bf16 GEMM (mma.sync + ldmatrix + NS-stage cp.async)
// BIAS: 0 none, 1 action table btab[action[row]][col] (stride N),
//       2 elementwise btab[row*ldbias + col].  ACT: 0 none, 1 tanh.
// ---------------------------------------------------------------------------
template <int BM, int BN, int WGM, int WGN, int NS, int NTHR, int BIAS, int ACT>
__global__ __launch_bounds__(NTHR)
void tc_gemm(const bf16* __restrict__ Ahi, const bf16* __restrict__ Alo,
             const bf16* __restrict__ Bhi, const bf16* __restrict__ Blo,
             const int* __restrict__ action, const float* __restrict__ btab,
             int ldbias, float* __restrict__ C, int N, int K)
{
    constexpr int WH  = BM / WGM, WN = BN / WGN;
    constexpr int MT  = WH / 16,  NTC = WN / 8;
    constexpr int STAGE   = (2 * BM + 2 * BN) * 80;
    constexpr int OFF_ALO = BM * 80;
    constexpr int OFF_BHI = 2 * BM * 80;
    constexpr int ROWS    = 2 * BM + 2 * BN;
    constexpr int CHUNKS  = ROWS * 4;          // 16B chunks per stage

    extern __shared__ char sm[];
    const int tid  = threadIdx.x;
    const int warp = tid >> 5, lane = tid & 31;
    const int warpM = warp / WGN, warpN = warp % WGN;
    const int lr = lane >> 2, lc = lane & 3;
    const int m0 = blockIdx.y * BM;
    const int n0 = blockIdx.x * BN;
    const uint32_t sb0 = smem_u32(sm);

    float acc[MT][NTC][4] = {};

    const int nc = K >> 5;    // BK=32

    auto load_stage = [&](int buf, int kblk) {
        uint32_t sb = sb0 + buf * STAGE;
        #pragma unroll
        for (int j = 0; j < CHUNKS / NTHR; j++) {
            int idx = tid + j * NTHR;
            int r = idx >> 2, w = idx & 3;
            const bf16* src;
            if (r < BM)               src = Ahi + (size_t)(m0 + r) * K;
            else if (r < 2 * BM)      src = Alo + (size_t)(m0 + r - BM) * K;
            else if (r < 2 * BM + BN) src = Bhi + (size_t)(n0 + r - 2 * BM) * K;
            else                      src = Blo + (size_t)(n0 + r - 2 * BM - BN) * K;
            cp16(sb + r * 80 + w * 16, src + kblk + w * 8);
        }
    };

    #pragma unroll
    for (int s = 0; s < NS - 1; s++) { load_stage(s, s * 32); cp_commit(); }

    for (int i = 0; i < nc; i++) {
        cp_wait<NS - 2>();
        __syncthreads();
        if (i + NS - 1 < nc) load_stage((i + NS - 1) % NS, (i + NS - 1) * 32);
        cp_commit();

        uint32_t sb = sb0 + (i % NS) * STAGE;
        #pragma unroll
        for (int kst = 0; kst < 2; kst++) {
            uint32_t ah[MT][4], al[MT][4], bh[NTC][2], bl[NTC][2];
            #pragma unroll
            for (int mi = 0; mi < MT; mi++) {
                uint32_t row = warpM * WH + mi * 16 + (lane & 15);
                uint32_t adr = sb + row * 80 + kst * 32 + ((lane >> 4) << 4);
                ldsm4(ah[mi][0], ah[mi][1], ah[mi][2], ah[mi][3], adr);
                ldsm4(al[mi][0], al[mi][1], al[mi][2], al[mi][3], adr + OFF_ALO);
            }
            #pragma unroll
            for (int pr = 0; pr < NTC / 2; pr++) {
                uint32_t row = warpN * WN + pr * 16 + ((lane >> 4) << 3) + (lane & 7);
                uint32_t adr = sb + OFF_BHI + row * 80 + kst * 32 + (((lane >> 3) & 1) << 4);
                ldsm4(bh[2 * pr][0], bh[2 * pr][1], bh[2 * pr + 1][0], bh[2 * pr + 1][1], adr);
                ldsm4(bl[2 * pr][0], bl[2 * pr][1], bl[2 * pr + 1][0], bl[2 * pr + 1][1],
                      adr + BN * 80);
            }
            #pragma unroll
            for (int mi = 0; mi < MT; mi++)
                #pragma unroll
                for (int ni = 0; ni < NTC; ni++) {
                    mma16816(acc[mi][ni], ah[mi], bh[ni]);
                    mma16816(acc[mi][ni], ah[mi], bl[ni]);
                    mma16816(acc[mi][ni], al[mi], bh[ni]);
                }
        }
    }

    // epilogue
    #pragma unroll
    for (int mi = 0; mi < MT; mi++) {
        int r0 = m0 + warpM * WH + mi * 16 + lr;
        const float* bt0 = nullptr; const float* bt1 = nullptr;
        if (BIAS == 1) {
            bt0 = btab + (size_t)action[r0] * N;
            bt1 = btab + (size_t)action[r0 + 8] * N;
        } else if (BIAS == 2) {
            bt0 = btab + (size_t)r0 * ldbias;
            bt1 = btab + (size_t)(r0 + 8) * ldbias;
        }
        #pragma unroll
        for (int ni = 0; ni < NTC; ni++) {
            int c = n0 + warpN * WN + ni * 8 + 2 * lc;
            float v0 = acc[mi][ni][0], v1 = acc[mi][ni][1];
            float v2 = acc[mi][ni][2], v3 = acc[mi][ni][3];
            if (BIAS != 0) { v0 += bt0[c]; v1 += bt0[c + 1]; v2 += bt1[c]; v3 += bt1[c + 1]; }
            if (ACT == 1)  { v0 = tanhf(v0); v1 = tanhf(v1); v2 = tanhf(v2); v3 = tanhf(v3); }
            *(float2*)(C + (size_t)r0 * N + c)       = make_float2(v0, v1);
            *(float2*)(C + (size_t)(r0 + 8) * N + c) = make_float2(v2, v3);
        }
    }
}

// ---------------------------------------------------------------------------
// vectorized split helper
// ---------------------------------------------------------------------------
__device__ __forceinline__ void split_chunk8(const float* src, bf16* hid, bf16* lod)
{
    float4 v0 = ((const float4*)src)[0];
    float4 v1 = ((const float4*)src)[1];
    bf16 h[8], l[8];
    split2(v0.x, h[0], l[0]); split2(v0.y, h[1], l[1]);
    split2(v0.z, h[2], l[2]); split2(v0.w, h[3], l[3]);
    split2(v1.x, h[4], l[4]); split2(v1.y, h[5], l[5]);
    split2(v1.z, h[6], l[6]); split2(v1.w, h[7], l[7]);
    *(uint4*)hid = *(uint4*)h;
    *(uint4*)lod = *(uint4*)l;
}

// ---------------------------------------------------------------------------
// MERGED prep kernel (one launch, blockIdx-partitioned; parts independent)
// ---------------------------------------------------------------------------
#define GCH   786432   // NGATES*KG/8
#define WINCH 131072   // HID*HID/8
#define WOUTCH 262144  // HID*2*HID/8
#define TOTCH (GCH + WINCH + WOUTCH)   // 1179648
#define NB_W   (TOTCH / 256)           // 4608
#define NB_EMB (NGATES / 8)            // 512
#define NB_GA  ((B * 192) / 256)       // 384
#define NB_ALL (NB_W + NB_EMB + NB_GA + 1)

__global__ __launch_bounds__(256)
void prep_all_kernel(const float* __restrict__ W_ih,
                     const float* __restrict__ W_hh,
                     const float* __restrict__ W_in,
                     const float* __restrict__ W_out,
                     const float* __restrict__ emb,
                     const float* __restrict__ b_ih,
                     const float* __restrict__ b_hh,
                     const float* __restrict__ feature,
                     const float* __restrict__ h0,
                     const unsigned int* __restrict__ maskw)
{
    const int bid = blockIdx.x;
    const int tid = threadIdx.x;

    if (bid < NB_W) {
        int c = bid * 256 + tid;
        if (c < GCH) {
            int n = c / 192, c8 = c % 192;
            const float* src = (c8 < 64) ? W_ih + (size_t)n * (EMB + FEAT) + EMB + c8 * 8
                                         : W_hh + (size_t)n * HID + (size_t)(c8 - 64) * 8;
            size_t d = (size_t)n * KG + c8 * 8;
            split_chunk8(src, gWg_hi + d, gWg_lo + d);
        } else if (c < GCH + WINCH) {
            size_t d = (size_t)(c - GCH) * 8;       // W_in -> Wcat rows [0,1024)
            split_chunk8(W_in + d, gWcat_hi + d, gWcat_lo + d);
        } else {
            size_t e8 = (size_t)(c - GCH - WINCH) * 8;   // offset in W_out [1024 x 2048]
            int n = (int)(e8 >> 11), col = (int)(e8 & 2047);
            const float* src = W_out + e8;
            if (col < HID) {
                size_t d = (size_t)n * HID + col;
                split_chunk8(src, gWoa_hi + d, gWoa_lo + d);
            } else {
                size_t d = (size_t)(HID + n) * HID + (col - HID);
                split_chunk8(src, gWcat_hi + d, gWcat_lo + d);
            }
        }
    } else if (bid < NB_W + NB_EMB) {
        __shared__ float s_emb[16 * EMB];
        int warp = tid >> 5, lane = tid & 31;
        for (int i = tid; i < 16 * EMB; i += 256) s_emb[i] = emb[i];
        __syncthreads();

        int n = (bid - NB_W) * 8 + warp;
        float w[8];
        #pragma unroll
        for (int j = 0; j < 8; j++) w[j] = W_ih[(size_t)n * (EMB + FEAT) + lane + j * 32];
        float bias = b_ih[n] + b_hh[n];
        for (int a = 0; a < 16; a++) {
            float d = 0.f;
            #pragma unroll
            for (int j = 0; j < 8; j++) d += w[j] * s_emb[a * EMB + lane + j * 32];
            #pragma unroll
            for (int o = 16; o; o >>= 1) d += __shfl_xor_sync(0xffffffffu, d, o);
            if (lane == 0) g_embW[a * NGATES + n] = d + bias;
        }
    } else if (bid < NB_W + NB_EMB + NB_GA) {
        int c = (bid - NB_W - NB_EMB) * 256 + tid;
        int b = c / 192, c8 = c % 192;
        const float* src = (c8 < 64) ? feature + (size_t)b * FEAT + c8 * 8
                                     : h0 + (size_t)b * HID + (size_t)(c8 - 64) * 8;
        size_t d = (size_t)b * KG + c8 * 8;
        split_chunk8(src, gAg_hi + d, gAg_lo + d);
    } else {
        int any = 0;
        for (int i = tid; i < 4096; i += 256)
            if (maskw[i] & 0xFFFFFF00u) any = 1;
        any = __syncthreads_or(any);
        if (tid == 0) g_mask_is_u8 = any;
    }
}

// ---------------------------------------------------------------------------
// LSTM elementwise; writes h1 splits (gAh) for the fused target|half2 GEMM
// ---------------------------------------------------------------------------
__global__ void lstm_cell_kernel(const float* __restrict__ c0,
                                 float* __restrict__ h1_out,
                                 float* __restrict__ c1_out)
{
    int idx = blockIdx.x * blockDim.x + threadIdx.x;   // B*HID
    int b = idx >> 10, j = idx & 1023;
    const float* g = g_gates + (size_t)b * NGATES;
    float gi = g[j];
    float gf = g[HID + j];
    float gg = g[2 * HID + j];
    float go = g[3 * HID + j];
    float c1 = sigmoidf_(gf) * c0[idx] + sigmoidf_(gi) * tanhf(gg);
    float h1 = sigmoidf_(go) * tanhf(c1);
    c1_out[idx] = c1;
    h1_out[idx] = h1;
    bf16 h, l;
    split2(h1, h, l);
    gAh_hi[idx] = h; gAh_lo[idx] = l;
}

// ---------------------------------------------------------------------------
// split-KV attention part: each CTA handles PPOS (=64) positions of one row.
// grid (B, NPART). Writes unnormalized partials + masked raw scores.
// smem: s_tgt[1024] | s_tile[2][8][1024] | s_attn[PPOS]
// ---------------------------------------------------------------------------
#define ATTNP_SMEM ((HID + 2 * 8 * HID + PPOS) * 4)
__global__ __launch_bounds__(256)
void attn_part_kernel(const float* __restrict__ ctx, const void* __restrict__ mask)
{
    extern __shared__ float a_sm[];
    float* s_tgt  = a_sm;                 // 1024
    float* s_tile = a_sm + HID;           // 2 * 8 * 1024
    float* s_attn = a_sm + HID + 16384;   // PPOS

    const int b = blockIdx.x;
    const int part = blockIdx.y;
    const int tid = threadIdx.x;
    const int warp = tid >> 5, lane = tid & 31;
    const int mask_u8 = g_mask_is_u8;
    const uint32_t tile_sm = smem_u32(s_tile);

    const unsigned char* mrow_u8 = (const unsigned char*)mask + (size_t)b * S + part * PPOS;
    const int*           mrow_i32 = (const int*)mask + (size_t)b * S + part * PPOS;
    const char* gbase = (const char*)(ctx + (size_t)b * S * HID + (size_t)part * PPOS * HID);

    {
        const float4* t4 = (const float4*)(g_th + (size_t)b * 2 * HID);
        ((float4*)s_tgt)[tid] = t4[tid];
    }

    auto load_chunk = [&](int buf, int c) {
        uint32_t sb = tile_sm + buf * 32768;
        const char* g = gbase + (size_t)c * 32768;
        #pragma unroll
        for (int j = 0; j < 8; j++) {
            int idx = tid + j * 256;
            cp16(sb + idx * 16, g + idx * 16);
        }
    };

    load_chunk(0, 0); cp_commit();

    float run_max = -1e30f, run_sum = 0.0f;
    float4 facc = make_float4(0.f, 0.f, 0.f, 0.f);
    const int NC = PPOS / 8;   // 8 chunks

    for (int c = 0; c < NC; c++) {
        if (c + 1 < NC) { load_chunk((c + 1) & 1, c + 1); cp_commit(); cp_wait<1>(); }
        else            { cp_wait<0>(); }
        __syncthreads();

        const float* tile = s_tile + (c & 1) * 8192;
        const int s0 = c * 8;

        {
            const float* trow = tile + warp * HID;
            float d = 0.f;
            #pragma unroll 8
            for (int i = lane; i < HID; i += 32) d += trow[i] * s_tgt[i];
            #pragma unroll
            for (int o = 16; o; o >>= 1) d += __shfl_xor_sync(0xffffffffu, d, o);
            if (lane == 0) {
                int s = s0 + warp;
                int m = mask_u8 ? (int)mrow_u8[s] : mrow_i32[s];
                if (m) d = -1e30f;
                s_attn[s] = d;
            }
        }
        __syncthreads();

        float cmax = run_max;
        #pragma unroll
        for (int i = 0; i < 8; i++) cmax = fmaxf(cmax, s_attn[s0 + i]);
        float scale = __expf(run_max - cmax);
        run_sum *= scale;
        facc.x *= scale; facc.y *= scale; facc.z *= scale; facc.w *= scale;
        float p[8];
        #pragma unroll
        for (int i = 0; i < 8; i++) { p[i] = __expf(s_attn[s0 + i] - cmax); run_sum += p[i]; }
        run_max = cmax;

        const int dbase = tid * 4;
        #pragma unroll
        for (int i = 0; i < 8; i++) {
            float4 v = *(const float4*)(tile + i * HID + dbase);
            facc.x += p[i] * v.x; facc.y += p[i] * v.y;
            facc.z += p[i] * v.z; facc.w += p[i] * v.w;
        }
        __syncthreads();
    }

    const int pi = b * NPART + part;
    if (tid == 0) { g_pm[pi] = run_max; g_ps[pi] = run_sum; }
    *(float4*)(g_pfacc + (size_t)pi * HID + tid * 4) = facc;
    if (tid < PPOS) g_scores[(size_t)b * S + part * PPOS + tid] = s_attn[tid];
}

// ---------------------------------------------------------------------------
// attention combine: merge NPART partials per batch row; write alpha + gAw.
// ---------------------------------------------------------------------------
__global__ __launch_bounds__(256)
void attn_combine_kernel(float* __restrict__ alpha_out)
{
    const int b = blockIdx.x, tid = threadIdx.x;
    float pm[NPART], ps[NPART];
    float m = -1e30f;
    #pragma unroll
    for (int k = 0; k < NPART; k++) { pm[k] = g_pm[b * NPART + k]; m = fmaxf(m, pm[k]); }
    float e[NPART], ssum = 0.f;
    #pragma unroll
    for (int k = 0; k < NPART; k++) {
        ps[k] = g_ps[b * NPART + k];
        e[k] = __expf(pm[k] - m);
        ssum += ps[k] * e[k];
    }
    float inv = 1.0f / ssum;

    float w[4] = {0.f, 0.f, 0.f, 0.f};
    #pragma unroll
    for (int k = 0; k < NPART; k++) {
        float4 f = *(const float4*)(g_pfacc + (size_t)(b * NPART + k) * HID + tid * 4);
        w[0] += f.x * e[k]; w[1] += f.y * e[k];
        w[2] += f.z * e[k]; w[3] += f.w * e[k];
    }
    size_t oo = (size_t)b * HID + tid * 4;
    #pragma unroll
    for (int j = 0; j < 4; j++) {
        bf16 h, l;
        split2(w[j] * inv, h, l);
        gAw_hi[oo + j] = h; gAw_lo[oo + j] = l;
    }

    float a = __expf(g_scores[(size_t)b * S + tid] - m) * inv;
    alpha_out[(size_t)b * S + tid] = a;
}

// ---------------------------------------------------------------------------
// logit = htilde @ W_dec^T + b_dec
// ---------------------------------------------------------------------------
__global__ void logit_kernel(const float* __restrict__ W_dec,
                             const float* __restrict__ b_dec,
                             float* __restrict__ out)
{
    int b = blockIdx.x;
    int w = threadIdx.x >> 5, lane = threadIdx.x & 31;
    const float* h = g_htilde + (size_t)b * HID;
    const float* wr = W_dec + (size_t)w * HID;
    float s = 0.f;
    #pragma unroll 8
    for (int i = lane; i < HID; i += 32) s += h[i] * wr[i];
    #pragma unroll
    for (int o = 16; o; o >>= 1) s += __shfl_xor_sync(0xffffffffu, s, o);
    if (lane == 0) out[(size_t)b * OUT_ACT + w] = s + b_dec[w];
}

// ---------------------------------------------------------------------------
// launch  (single stream)
// ---------------------------------------------------------------------------
extern "C" void kernel_launch(void* const* d_in, const int* in_sizes, int n_in,
                              void* d_out, int out_size)
{
    const int*   action   = (const int*)d_in[0];
    const float* feature  = (const float*)d_in[1];
    const float* h_0      = (const float*)d_in[2];
    const float* c_0      = (const float*)d_in[3];
    const float* ctx      = (const float*)d_in[4];
    const void*  ctx_mask = d_in[5];
    const float* embedding= (const float*)d_in[6];
    const float* W_ih     = (const float*)d_in[7];
    const float* W_hh     = (const float*)d_in[8];
    const float* b_ih     = (const float*)d_in[9];
    const float* b_hh     = (const float*)d_in[10];
    const float* W_in     = (const float*)d_in[11];
    const float* W_out    = (const float*)d_in[12];
    const float* W_dec    = (const float*)d_in[13];
    const float* b_dec    = (const float*)d_in[14];

    float* out   = (float*)d_out;
    float* h1    = out;
    float* c1    = out + (size_t)B * HID;
    float* alpha = out + (size_t)2 * B * HID;
    float* logit = alpha + (size_t)B * S;

    void* p;
    cudaGetSymbolAddress(&p, g_gates);   float* gates  = (float*)p;
    cudaGetSymbolAddress(&p, g_th);      float* th     = (float*)p;
    cudaGetSymbolAddress(&p, g_htilde);  float* htilde = (float*)p;
    cudaGetSymbolAddress(&p, g_embW);    float* embW   = (float*)p;
    bf16 *ag_hi, *ag_lo, *wg_hi, *wg_lo, *ah_hi, *ah_lo, *aw_hi, *aw_lo;
    bf16 *wcat_hi, *wcat_lo, *woa_hi, *woa_lo;
    cudaGetSymbolAddress(&p, gAg_hi);   ag_hi   = (bf16*)p;
    cudaGetSymbolAddress(&p, gAg_lo);   ag_lo   = (bf16*)p;
    cudaGetSymbolAddress(&p, gWg_hi);   wg_hi   = (bf16*)p;
    cudaGetSymbolAddress(&p, gWg_lo);   wg_lo   = (bf16*)p;
    cudaGetSymbolAddress(&p, gAh_hi);   ah_hi   = (bf16*)p;
    cudaGetSymbolAddress(&p, gAh_lo);   ah_lo   = (bf16*)p;
    cudaGetSymbolAddress(&p, gAw_hi);   aw_hi   = (bf16*)p;
    cudaGetSymbolAddress(&p, gAw_lo);   aw_lo   = (bf16*)p;
    cudaGetSymbolAddress(&p, gWcat_hi); wcat_hi = (bf16*)p;
    cudaGetSymbolAddress(&p, gWcat_lo); wcat_lo = (bf16*)p;
    cudaGetSymbolAddress(&p, gWoa_hi);  woa_hi  = (bf16*)p;
    cudaGetSymbolAddress(&p, gWoa_lo);  woa_lo  = (bf16*)p;

    const int SMEM_GATES = 2 * (2 * 128 + 2 * 64) * 80;    // 61440
    const int SMEM_6464  = 3 * (2 * 64 + 2 * 64) * 80;     // 61440
    const int SMEM_SMALL = 3 * (2 * 64 + 2 * 32) * 80;     // 46080
    static bool attr_done = false;
    if (!attr_done) {
        cudaFuncSetAttribute((const void*)tc_gemm<128, 64, 4, 4, 2, 512, 1, 0>,
                             cudaFuncAttributeMaxDynamicSharedMemorySize, SMEM_GATES);
        cudaFuncSetAttribute((const void*)tc_gemm<64, 64, 2, 4, 3, 256, 0, 0>,
                             cudaFuncAttributeMaxDynamicSharedMemorySize, SMEM_6464);
        cudaFuncSetAttribute((const void*)tc_gemm<64, 32, 4, 2, 3, 256, 2, 1>,
                             cudaFuncAttributeMaxDynamicSharedMemorySize, SMEM_SMALL);
        cudaFuncSetAttribute((const void*)attn_part_kernel,
                             cudaFuncAttributeMaxDynamicSharedMemorySize, ATTNP_SMEM);
        attr_done = true;
    }

    // 0: all prep in ONE launch
    prep_all_kernel<<<NB_ALL, 256>>>(W_ih, W_hh, W_in, W_out, embedding,
                                     b_ih, b_hh, feature, h_0,
                                     (const unsigned int*)ctx_mask);

    // 1: gates GEMM — champion config
    tc_gemm<128, 64, 4, 4, 2, 512, 1, 0><<<dim3(NGATES / 64, B / 128), 512, SMEM_GATES>>>(
        ag_hi, ag_lo, wg_hi, wg_lo, action, embW, 0, gates, NGATES, KG);

    // 2: LSTM elementwise -> h1, c1 (+ h1 splits)
    lstm_cell_kernel<<<(B * HID) / 256, 256>>>(c_0, h1, c1);

    // 3: fused [target | half2] = h1 @ [W_in ; W_out[:,1024:]]^T  (64x64 tiles)
    tc_gemm<64, 64, 2, 4, 3, 256, 0, 0><<<dim3(2 * HID / 64, B / 64), 256, SMEM_6464>>>(
        ah_hi, ah_lo, wcat_hi, wcat_lo, nullptr, nullptr, 0, th, 2 * HID, HID);

    // 4: split-KV attention parts (grid B x NPART)
    attn_part_kernel<<<dim3(B, NPART), 256, ATTNP_SMEM>>>(ctx, ctx_mask);

    // 5: combine partials -> alpha, weighted(split)
    attn_combine_kernel<<<B, 256>>>(alpha);

    // 6: htilde = tanh(weighted @ W_out[:, :1024]^T + half2)
    tc_gemm<64, 32, 4, 2, 3, 256, 2, 1><<<dim3(HID / 32, B / 64), 256, SMEM_SMALL>>>(
        aw_hi, aw_lo, woa_hi, woa_lo, nullptr, th + HID, 2 * HID, htilde, HID, HID);

    // 7: logit
    logit_kernel<<<B, OUT_ACT * 32>>>(W_dec, b_dec, logit);
}